// round 15
// baseline (speedup 1.0000x reference)
#include <cuda_runtime.h>
#include <math.h>

#define BB 64
#define DD 256
#define HH 512
#define NN 16384
#define MM 64
#define SS 3
#define EPSF 1e-4f
#define G4H 2048
#define KTOT 832            // D + M + H
#define KSPLIT 13           // 832 = 13 * 64
#define CHUNKS 64
#define ROWS_PER_CHUNK (NN / CHUNKS)   // 256

// ---------------- scratch (device globals, no allocation) ----------------
__device__ float g_k[2][BB * MM];        // tanh keys (read=0, write=1)
__device__ float g_s3[2][BB * SS];       // shift softmax
__device__ float g_binvnk[2][BB];        // beta / nk
__device__ float g_g[2][BB];
__device__ float g_gamma[2][BB];
__device__ float g_e[BB * MM];
__device__ float g_a[BB * MM];
__device__ float g_logits[BB * NN];
__device__ float g_Mpart[CHUNKS * BB * MM];
__device__ float g_gates[KSPLIT * BB * G4H];   // K-split partials (chunk 4 unused)

// ============ head params: warp-per-row coalesced GEMV, 16 warps ==========
// Read phase (Ww==null): h comes from hvec (h_tm1).
// Write phase (Ww!=null): reduces Mpart->Mread in smem, adds the Mread gate
// contribution inline (replaces gates_mr + mread_reduce), computes LSTM,
// then the head-param GEMV.
__global__ void head_params_kernel(const float* __restrict__ hvec,
                                   const float* __restrict__ Wk, const float* __restrict__ bk,
                                   const float* __restrict__ Wc, const float* __restrict__ bc,
                                   const float* __restrict__ Ws, const float* __restrict__ bs,
                                   int phase,
                                   const float* __restrict__ Ww, const float* __restrict__ bw,
                                   const float* __restrict__ c_tm1,
                                   const float* __restrict__ b_ih,
                                   const float* __restrict__ b_hh,
                                   const float* __restrict__ W_ih,
                                   float* __restrict__ d_out)
{
    int b = blockIdx.x;
    int t = threadIdx.x;                 // 512 threads = 16 warps
    int warp = t >> 5, lane = t & 31;
    __shared__ float sh[HH];
    __shared__ float sk[MM];
    __shared__ float sc[SS];
    __shared__ float ssl[SS];
    __shared__ __align__(16) float mr[MM];

    if (Ww) {
        cudaGridDependencySynchronize();     // g_Mpart ready (mread_partial)
        // ---- Mread reduce: 64 threads sum the 64 chunk partials ----
        if (t < MM) {
            float s = 0.f;
            #pragma unroll 8
            for (int cz = 0; cz < CHUNKS; cz++)
                s += g_Mpart[((size_t)cz * BB + b) * MM + t];
            mr[t] = s;
        }
        __syncthreads();

        // ---- fused LSTM: thread t handles hidden index j = t ----
        int j = t;
        float gv[4];
        #pragma unroll
        for (int g = 0; g < 4; g++) {
            int col = g * HH + j;
            float s = b_ih[col] + b_hh[col];
            #pragma unroll
            for (int s4 = 0; s4 < KSPLIT; s4++)
                if (s4 != 4) s += g_gates[((size_t)s4 * BB + b) * G4H + col];
            // inline Mread-chunk contribution (k in [DD, DD+MM))
            const float4* wrow = (const float4*)(W_ih + (size_t)col * (DD + MM) + DD);
            const float4* mr4 = (const float4*)mr;
            #pragma unroll
            for (int m4 = 0; m4 < MM / 4; m4++) {
                float4 wv = wrow[m4];
                float4 mv = mr4[m4];
                s += wv.x * mv.x + wv.y * mv.y + wv.z * mv.z + wv.w * mv.w;
            }
            gv[g] = s;
        }
        float si = 1.f / (1.f + expf(-gv[0]));
        float sf = 1.f / (1.f + expf(-gv[1]));
        float so = 1.f / (1.f + expf(-gv[3]));
        float ct = sf * c_tm1[b * HH + j] + si * tanhf(gv[2]);
        float ht = so * tanhf(ct);
        d_out[b * HH + j] = ht;               // h_t
        d_out[BB * HH + b * HH + j] = ct;     // c_t
        sh[j] = ht;                           // straight into the GEMV input
    } else {
        sh[t] = hvec[b * HH + t];
    }
    __syncthreads();

    int nrows = Ww ? 198 : 70;
    for (int rr = warp; rr < nrows; rr += 16) {
        const float* w;
        if (rr < 64)       w = Wk + rr * HH;
        else if (rr < 67)  w = Wc + (rr - 64) * HH;
        else if (rr < 70)  w = Ws + (rr - 67) * HH;
        else               w = Ww + (rr - 70) * HH;
        float acc = 0.f;
        #pragma unroll
        for (int it = 0; it < 16; it++) {
            int kx = lane + it * 32;
            acc += sh[kx] * w[kx];
        }
        #pragma unroll
        for (int o = 16; o > 0; o >>= 1) acc += __shfl_down_sync(0xffffffffu, acc, o);
        if (lane == 0) {
            if (rr < 64) {
                float kv = tanhf(acc + bk[rr]);
                sk[rr] = kv;
                g_k[phase][b * MM + rr] = kv;
            } else if (rr < 67) {
                sc[rr - 64] = acc + bc[rr - 64];
            } else if (rr < 70) {
                ssl[rr - 67] = acc + bs[rr - 67];
            } else {
                int r = rr - 70;
                float v = acc + bw[r];
                if (r < MM) g_e[b * MM + r] = 1.f / (1.f + expf(-v));
                else        g_a[b * MM + (r - MM)] = v;
            }
        }
    }
    __syncthreads();

    if (t == 0) {
        float mx = fmaxf(ssl[0], fmaxf(ssl[1], ssl[2]));
        float e0 = expf(ssl[0] - mx), e1 = expf(ssl[1] - mx), e2 = expf(ssl[2] - mx);
        float sum = e0 + e1 + e2;
        g_s3[phase][b * SS + 0] = e0 / sum;
        g_s3[phase][b * SS + 1] = e1 / sum;
        g_s3[phase][b * SS + 2] = e2 / sum;
        float beta  = fmaxf(sc[0], 0.f) + EPSF;
        float gv    = 1.f / (1.f + expf(-sc[1]));
        float gamma = fmaxf(sc[2], 0.f) + 1.f + EPSF;
        float ns = 0.f;
        for (int i = 0; i < MM; i++) ns += sk[i] * sk[i];
        float nk = sqrtf(ns) + EPSF;
        g_binvnk[phase][b] = beta / nk;
        g_g[phase][b] = gv;
        g_gamma[phase][b] = gamma;
    }
    cudaTriggerProgrammaticLaunchCompletion();
}

// ------------- logits: PDL prefetch of memory before grid sync ------------
__global__ void logits_kernel(const float* __restrict__ memory, int phase)
{
    int b = blockIdx.y;
    int warp = threadIdx.x >> 5, lane = threadIdx.x & 31;
    int rbase = blockIdx.x * 64 + warp * 8 + (lane >> 4);   // 8 rows per warp
    const float4* mem4 = (const float4*)(memory + (size_t)b * NN * MM);

    // memory is a kernel INPUT (no dependency) — stream it before the sync
    float4 v[4];
    #pragma unroll
    for (int i = 0; i < 4; i++)
        v[i] = mem4[(size_t)(rbase + 2 * i) * 16 + (lane & 15)];

    cudaGridDependencySynchronize();

    __shared__ float sk[MM];
    if (threadIdx.x < MM) sk[threadIdx.x] = g_k[phase][b * MM + threadIdx.x];
    __syncthreads();
    float4 kq = ((const float4*)sk)[lane & 15];
    float binvnk = g_binvnk[phase][b];
    float* out = g_logits + b * NN;

    #pragma unroll
    for (int i = 0; i < 4; i++) {
        float d = kq.x * v[i].x + kq.y * v[i].y + kq.z * v[i].z + kq.w * v[i].w;
        float s = v[i].x * v[i].x + v[i].y * v[i].y + v[i].z * v[i].z + v[i].w * v[i].w;
        #pragma unroll
        for (int o = 8; o > 0; o >>= 1) {
            d += __shfl_xor_sync(0xffffffffu, d, o);
            s += __shfl_xor_sync(0xffffffffu, s, o);
        }
        if ((lane & 15) == 0) out[rbase + 2 * i] = binvnk * d / (sqrtf(s) + EPSF);
    }
    cudaTriggerProgrammaticLaunchCompletion();
}

// ---- addressing (head only): softmax -> interp -> conv -> sharpen -> norm ----
__global__ __launch_bounds__(1024, 1)
void address_kernel(const float* __restrict__ w_tm1, float* __restrict__ head_out, int phase)
{
    extern __shared__ float sInter[];     // NN floats (64 KB)
    __shared__ float red[32];
    int b = blockIdx.x, t = threadIdx.x;
    int warp = t >> 5, lane = t & 31;

    cudaGridDependencySynchronize();
    const float* lg = g_logits + b * NN;

    float v[16];
    float lmax = -1e30f;
    #pragma unroll
    for (int e = 0; e < 16; e++) { v[e] = lg[e * 1024 + t]; lmax = fmaxf(lmax, v[e]); }
    #pragma unroll
    for (int o = 16; o > 0; o >>= 1) lmax = fmaxf(lmax, __shfl_xor_sync(0xffffffffu, lmax, o));
    if (lane == 0) red[warp] = lmax;
    __syncthreads();
    if (warp == 0) {
        float m = red[lane];
        #pragma unroll
        for (int o = 16; o > 0; o >>= 1) m = fmaxf(m, __shfl_xor_sync(0xffffffffu, m, o));
        red[lane] = m;
    }
    __syncthreads();
    float gmax = red[0];

    float lsum = 0.f;
    #pragma unroll
    for (int e = 0; e < 16; e++) { float ev = __expf(v[e] - gmax); v[e] = ev; lsum += ev; }
    #pragma unroll
    for (int o = 16; o > 0; o >>= 1) lsum += __shfl_xor_sync(0xffffffffu, lsum, o);
    __syncthreads();                      // red reusable
    if (lane == 0) red[warp] = lsum;
    __syncthreads();
    if (warp == 0) {
        float s = red[lane];
        #pragma unroll
        for (int o = 16; o > 0; o >>= 1) s += __shfl_xor_sync(0xffffffffu, s, o);
        red[lane] = s;
    }
    __syncthreads();
    float inv = 1.f / red[0];

    float gg = g_g[phase][b];
    const float* wt = w_tm1 + b * NN;
    #pragma unroll
    for (int e = 0; e < 16; e++) {
        int idx = e * 1024 + t;
        sInter[idx] = gg * v[e] * inv + (1.f - gg) * wt[idx];
    }
    __syncthreads();

    float s0 = g_s3[phase][b * SS + 0];
    float s1 = g_s3[phase][b * SS + 1];
    float s2 = g_s3[phase][b * SS + 2];
    float gamma = g_gamma[phase][b];
    float ssum = 0.f;
    #pragma unroll
    for (int e = 0; e < 16; e++) {
        int idx = e * 1024 + t;
        float c = s0 * sInter[(idx + NN - 2) & (NN - 1)]
                + s1 * sInter[(idx + NN - 1) & (NN - 1)]
                + s2 * sInter[idx];
        float sp = __powf(fmaxf(c, 1e-8f), gamma);
        v[e] = sp; ssum += sp;
    }
    #pragma unroll
    for (int o = 16; o > 0; o >>= 1) ssum += __shfl_xor_sync(0xffffffffu, ssum, o);
    __syncthreads();
    if (lane == 0) red[warp] = ssum;
    __syncthreads();
    if (warp == 0) {
        float s = red[lane];
        #pragma unroll
        for (int o = 16; o > 0; o >>= 1) s += __shfl_xor_sync(0xffffffffu, s, o);
        red[lane] = s;
    }
    __syncthreads();
    float invs = 1.f / red[0];
    float* out = head_out + b * NN;
    #pragma unroll
    for (int e = 0; e < 16; e++) out[e * 1024 + t] = v[e] * invs;
    cudaTriggerProgrammaticLaunchCompletion();
}

// -------------- M_read partials (streaming body unchanged) ----------------
__global__ void mread_partial_kernel(const float* __restrict__ memory,
                                     const float* __restrict__ head)
{
    int b = blockIdx.y, cz = blockIdx.x;
    int t = threadIdx.x;          // 256
    int r = t >> 4, q = t & 15;   // 16 rows in flight x 16 float4 lanes
    cudaGridDependencySynchronize();
    const float4* mem4 = (const float4*)(memory + (size_t)b * NN * MM);
    const float* hd = head + b * NN;
    float4 acc = make_float4(0.f, 0.f, 0.f, 0.f);
    int n0 = cz * ROWS_PER_CHUNK;
    for (int i = 0; i < ROWS_PER_CHUNK; i += 16) {
        int n = n0 + i + r;
        float w = hd[n];
        float4 mv = mem4[(size_t)n * 16 + q];
        acc.x += w * mv.x; acc.y += w * mv.y; acc.z += w * mv.z; acc.w += w * mv.w;
    }
    __shared__ float4 sm[16][16];
    sm[r][q] = acc;
    __syncthreads();
    if (t < 16) {
        float4 s = sm[0][t];
        #pragma unroll
        for (int r2 = 1; r2 < 16; r2++) {
            float4 vv = sm[r2][t];
            s.x += vv.x; s.y += vv.y; s.z += vv.z; s.w += vv.w;
        }
        ((float4*)(g_Mpart + ((size_t)cz * BB + b) * MM))[t] = s;
    }
    cudaTriggerProgrammaticLaunchCompletion();
}

// ---------- gates GEMM tile body (one 64-wide K chunk = ky) ---------------
__device__ __forceinline__ void gates_chunk(const float* __restrict__ inp,
                                            const float* __restrict__ h_tm1,
                                            const float* __restrict__ W_ih,
                                            const float* __restrict__ W_hh,
                                            int jbase, int ky, int t)
{
    __shared__ __align__(16) float xs[32][68];   // [kk][batch]
    __shared__ __align__(16) float ws[32][68];   // [kk][jrow]
    int tj = t & 15, tb = t >> 4;
    float acc[4][4];
    #pragma unroll
    for (int jj = 0; jj < 4; jj++)
        #pragma unroll
        for (int bb2 = 0; bb2 < 4; bb2++) acc[jj][bb2] = 0.f;

    int kend = (ky + 1) * 64;
    for (int k0 = ky * 64; k0 < kend; k0 += 32) {
        #pragma unroll
        for (int li = t; li < 2048; li += 256) {
            int row = li >> 5, kk = li & 31, k = k0 + kk;
            float xv;
            if (k < DD)            xv = inp[row * DD + k];
            else                   xv = h_tm1[row * HH + (k - DD - MM)];
            xs[kk][row] = xv;
            int j = jbase + row;
            float wv = (k < DD + MM) ? W_ih[j * (DD + MM) + k]
                                     : W_hh[j * HH + (k - DD - MM)];
            ws[kk][row] = wv;
        }
        __syncthreads();
        #pragma unroll
        for (int kk = 0; kk < 32; kk++) {
            float4 wr = *(const float4*)&ws[kk][tj * 4];
            float4 xr = *(const float4*)&xs[kk][tb * 4];
            acc[0][0] += wr.x * xr.x; acc[0][1] += wr.x * xr.y;
            acc[0][2] += wr.x * xr.z; acc[0][3] += wr.x * xr.w;
            acc[1][0] += wr.y * xr.x; acc[1][1] += wr.y * xr.y;
            acc[1][2] += wr.y * xr.z; acc[1][3] += wr.y * xr.w;
            acc[2][0] += wr.z * xr.x; acc[2][1] += wr.z * xr.y;
            acc[2][2] += wr.z * xr.z; acc[2][3] += wr.z * xr.w;
            acc[3][0] += wr.w * xr.x; acc[3][1] += wr.w * xr.y;
            acc[3][2] += wr.w * xr.z; acc[3][3] += wr.w * xr.w;
        }
        __syncthreads();
    }
    #pragma unroll
    for (int jj = 0; jj < 4; jj++) {
        int j = jbase + tj * 4 + jj;
        #pragma unroll
        for (int bb2 = 0; bb2 < 4; bb2++) {
            int b = tb * 4 + bb2;
            g_gates[((size_t)ky * BB + b) * G4H + j] = acc[jj][bb2];
        }
    }
}

// gates_main: the 12 chunks that need only inp + h_tm1 (chunk 4 handled
// inline by head_params_w). ky==4 never occurs here.
__global__ void gates_main_kernel(const float* __restrict__ inp,
                                  const float* __restrict__ h_tm1,
                                  const float* __restrict__ W_ih,
                                  const float* __restrict__ W_hh)
{
    int ky = blockIdx.y < 4 ? blockIdx.y : blockIdx.y + 1;   // skip chunk 4
    gates_chunk(inp, h_tm1, W_ih, W_hh, blockIdx.x * 64, ky, threadIdx.x);
}

// ------------- memory update: PDL prefetch of memory ----------------------
__global__ void memupdate_kernel(const float* __restrict__ memory,
                                 const float* __restrict__ whead,
                                 float* __restrict__ mout)
{
    size_t i4 = (size_t)blockIdx.x * 256 + threadIdx.x;  // total BB*NN*MM/4
    int b   = (int)(i4 >> 18);                // NN*MM/4 = 262144
    int rem = (int)(i4 & 262143);
    int n   = rem >> 4;
    int mq  = rem & 15;
    float4 mv = ((const float4*)memory)[i4];   // input tensor: no dependency
    cudaGridDependencySynchronize();
    float w = whead[b * NN + n];
    float4 ev = ((const float4*)(g_e + b * MM))[mq];
    float4 av = ((const float4*)(g_a + b * MM))[mq];
    float4 o;
    o.x = mv.x * (1.f - w * ev.x) + w * av.x;
    o.y = mv.y * (1.f - w * ev.y) + w * av.y;
    o.z = mv.z * (1.f - w * ev.z) + w * av.z;
    o.w = mv.w * (1.f - w * ev.w) + w * av.w;
    __stcs(((float4*)mout) + i4, o);
}

// ---------------- side-stream resources (host-side only) ------------------
struct SideStream {
    cudaStream_t s;
    cudaEvent_t fork_ev, join_ev;
    SideStream() {
        cudaStreamCreateWithFlags(&s, cudaStreamNonBlocking);
        cudaEventCreateWithFlags(&fork_ev, cudaEventDisableTiming);
        cudaEventCreateWithFlags(&join_ev, cudaEventDisableTiming);
    }
};

// ---------------- PDL launch helper ---------------------------------------
template <typename F, typename... Args>
static inline void launch_pdl(F kernel, dim3 grid, dim3 block, size_t smem, Args... args)
{
    cudaLaunchConfig_t cfg = {};
    cfg.gridDim = grid;
    cfg.blockDim = block;
    cfg.dynamicSmemBytes = smem;
    cfg.stream = 0;
    cudaLaunchAttribute attr[1];
    attr[0].id = cudaLaunchAttributeProgrammaticStreamSerialization;
    attr[0].val.programmaticStreamSerializationAllowed = 1;
    cfg.attrs = attr;
    cfg.numAttrs = 1;
    cudaLaunchKernelEx(&cfg, kernel, args...);
}

// --------------------------------- launch ---------------------------------
extern "C" void kernel_launch(void* const* d_in, const int* in_sizes, int n_in,
                              void* d_out_v, int out_size)
{
    const float* inp       = (const float*)d_in[0];
    const float* h_tm1     = (const float*)d_in[1];
    const float* c_tm1     = (const float*)d_in[2];
    const float* read_tm1  = (const float*)d_in[3];
    const float* write_tm1 = (const float*)d_in[4];
    const float* memory    = (const float*)d_in[5];
    const float* W_ih = (const float*)d_in[6];
    const float* b_ih = (const float*)d_in[7];
    const float* W_hh = (const float*)d_in[8];
    const float* b_hh = (const float*)d_in[9];
    const float* W_rk = (const float*)d_in[10];
    const float* b_rk = (const float*)d_in[11];
    const float* W_wk = (const float*)d_in[12];
    const float* b_wk = (const float*)d_in[13];
    const float* W_rc = (const float*)d_in[14];
    const float* b_rc = (const float*)d_in[15];
    const float* W_wc = (const float*)d_in[16];
    const float* b_wc = (const float*)d_in[17];
    const float* W_rs = (const float*)d_in[18];
    const float* b_rs = (const float*)d_in[19];
    const float* W_ws = (const float*)d_in[20];
    const float* b_ws = (const float*)d_in[21];
    const float* W_w  = (const float*)d_in[22];
    const float* b_w  = (const float*)d_in[23];

    float* d_out = (float*)d_out_v;
    float* rhead  = d_out + 2 * BB * HH;
    float* whead  = rhead + (size_t)BB * NN;
    float* mout   = whead + (size_t)BB * NN;
    (void)in_sizes; (void)n_in; (void)out_size;

    static SideStream side;               // created once (host resources only)

    cudaFuncSetAttribute(address_kernel,
                         cudaFuncAttributeMaxDynamicSharedMemorySize, NN * 4);

    // ---- fork: gates_main runs concurrently with the read phase ----
    cudaEventRecord(side.fork_ev, 0);
    cudaStreamWaitEvent(side.s, side.fork_ev, 0);
    gates_main_kernel<<<dim3(G4H / 64, KSPLIT - 1), 256, 0, side.s>>>(inp, h_tm1, W_ih, W_hh);
    cudaEventRecord(side.join_ev, side.s);

    // ---- read phase (main stream, PDL-chained) ----
    head_params_kernel<<<BB, 512>>>(h_tm1, W_rk, b_rk, W_rc, b_rc, W_rs, b_rs, 0,
                                    nullptr, nullptr, nullptr, nullptr, nullptr,
                                    nullptr, nullptr);
    launch_pdl(logits_kernel, dim3(NN / 64, BB), dim3(256), 0, memory, 0);
    launch_pdl(address_kernel, dim3(BB), dim3(1024), (size_t)NN * 4,
               (const float*)read_tm1, rhead, 0);
    launch_pdl(mread_partial_kernel, dim3(CHUNKS, BB), dim3(256), 0,
               memory, (const float*)rhead);

    // ---- write phase: head_params_w = Mread reduce + gates chunk 4 +
    //      LSTM + head params, all in one kernel ----
    cudaStreamWaitEvent(0, side.join_ev, 0);     // g_gates (main 12 chunks) ready
    launch_pdl(head_params_kernel, dim3(BB), dim3(512), 0,
               (const float*)nullptr, W_wk, b_wk, W_wc, b_wc, W_ws, b_ws, 1,
               W_w, b_w, c_tm1, b_ih, b_hh, W_ih, d_out);
    launch_pdl(logits_kernel, dim3(NN / 64, BB), dim3(256), 0, memory, 1);
    launch_pdl(address_kernel, dim3(BB), dim3(1024), (size_t)NN * 4,
               (const float*)write_tm1, whead, 1);
    launch_pdl(memupdate_kernel, dim3((BB * NN * MM / 4) / 256), dim3(256), 0,
               memory, (const float*)whead, mout);
}

// round 16
// speedup vs baseline: 1.0335x; 1.0335x over previous
#include <cuda_runtime.h>
#include <math.h>

#define BB 64
#define DD 256
#define HH 512
#define NN 16384
#define MM 64
#define SS 3
#define EPSF 1e-4f
#define G4H 2048
#define KTOT 832            // D + M + H
#define KSPLIT 13           // 832 = 13 * 64
#define CHUNKS 64
#define ROWS_PER_CHUNK (NN / CHUNKS)   // 256

// ---------------- scratch (device globals, no allocation) ----------------
__device__ float g_k[2][BB * MM];        // tanh keys (read=0, write=1)
__device__ float g_s3[2][BB * SS];       // shift softmax
__device__ float g_binvnk[2][BB];        // beta / nk
__device__ float g_g[2][BB];
__device__ float g_gamma[2][BB];
__device__ float g_e[BB * MM];
__device__ float g_a[BB * MM];
__device__ float g_logits[BB * NN];
__device__ float g_Mpart[CHUNKS * BB * MM];
__device__ float g_Mread[BB * MM];
__device__ float g_gates[KSPLIT * BB * G4H];   // K-split partials (no bias)

// ============ head params: warp-per-row coalesced GEMV, 16 warps ==========
// Read phase (Ww==null): h comes from hvec (h_tm1).
// Write phase (Ww!=null): h_t computed HERE (fused LSTM) from g_gates.
__global__ void head_params_kernel(const float* __restrict__ hvec,
                                   const float* __restrict__ Wk, const float* __restrict__ bk,
                                   const float* __restrict__ Wc, const float* __restrict__ bc,
                                   const float* __restrict__ Ws, const float* __restrict__ bs,
                                   int phase,
                                   const float* __restrict__ Ww, const float* __restrict__ bw,
                                   const float* __restrict__ c_tm1,
                                   const float* __restrict__ b_ih,
                                   const float* __restrict__ b_hh,
                                   float* __restrict__ d_out)
{
    int b = blockIdx.x;
    int t = threadIdx.x;                 // 512 threads = 16 warps
    int warp = t >> 5, lane = t & 31;
    __shared__ float sh[HH];
    __shared__ float sk[MM];
    __shared__ float sc[SS];
    __shared__ float ssl[SS];

    if (Ww) {
        // ---- fused LSTM: thread t handles hidden index j = t ----
        int j = t;
        float gv[4];
        #pragma unroll
        for (int g = 0; g < 4; g++) {
            int col = g * HH + j;
            float s = b_ih[col] + b_hh[col];
            #pragma unroll
            for (int s4 = 0; s4 < KSPLIT; s4++)
                s += g_gates[((size_t)s4 * BB + b) * G4H + col];
            gv[g] = s;
        }
        float si = 1.f / (1.f + expf(-gv[0]));
        float sf = 1.f / (1.f + expf(-gv[1]));
        float so = 1.f / (1.f + expf(-gv[3]));
        float ct = sf * c_tm1[b * HH + j] + si * tanhf(gv[2]);
        float ht = so * tanhf(ct);
        d_out[b * HH + j] = ht;               // h_t
        d_out[BB * HH + b * HH + j] = ct;     // c_t
        sh[j] = ht;                           // straight into the GEMV input
    } else {
        sh[t] = hvec[b * HH + t];
    }
    __syncthreads();

    int nrows = Ww ? 198 : 70;
    for (int rr = warp; rr < nrows; rr += 16) {
        const float* w;
        if (rr < 64)       w = Wk + rr * HH;
        else if (rr < 67)  w = Wc + (rr - 64) * HH;
        else if (rr < 70)  w = Ws + (rr - 67) * HH;
        else               w = Ww + (rr - 70) * HH;
        float acc = 0.f;
        #pragma unroll
        for (int it = 0; it < 16; it++) {
            int kx = lane + it * 32;
            acc += sh[kx] * w[kx];
        }
        #pragma unroll
        for (int o = 16; o > 0; o >>= 1) acc += __shfl_down_sync(0xffffffffu, acc, o);
        if (lane == 0) {
            if (rr < 64) {
                float kv = tanhf(acc + bk[rr]);
                sk[rr] = kv;
                g_k[phase][b * MM + rr] = kv;
            } else if (rr < 67) {
                sc[rr - 64] = acc + bc[rr - 64];
            } else if (rr < 70) {
                ssl[rr - 67] = acc + bs[rr - 67];
            } else {
                int r = rr - 70;
                float v = acc + bw[r];
                if (r < MM) g_e[b * MM + r] = 1.f / (1.f + expf(-v));
                else        g_a[b * MM + (r - MM)] = v;
            }
        }
    }
    __syncthreads();

    if (t == 0) {
        float mx = fmaxf(ssl[0], fmaxf(ssl[1], ssl[2]));
        float e0 = expf(ssl[0] - mx), e1 = expf(ssl[1] - mx), e2 = expf(ssl[2] - mx);
        float sum = e0 + e1 + e2;
        g_s3[phase][b * SS + 0] = e0 / sum;
        g_s3[phase][b * SS + 1] = e1 / sum;
        g_s3[phase][b * SS + 2] = e2 / sum;
        float beta  = fmaxf(sc[0], 0.f) + EPSF;
        float gv    = 1.f / (1.f + expf(-sc[1]));
        float gamma = fmaxf(sc[2], 0.f) + 1.f + EPSF;
        float ns = 0.f;
        for (int i = 0; i < MM; i++) ns += sk[i] * sk[i];
        float nk = sqrtf(ns) + EPSF;
        g_binvnk[phase][b] = beta / nk;
        g_g[phase][b] = gv;
        g_gamma[phase][b] = gamma;
    }
    cudaTriggerProgrammaticLaunchCompletion();
}

// ------------- logits: PDL prefetch of memory before grid sync ------------
__global__ void logits_kernel(const float* __restrict__ memory, int phase)
{
    int b = blockIdx.y;
    int warp = threadIdx.x >> 5, lane = threadIdx.x & 31;
    int rbase = blockIdx.x * 64 + warp * 8 + (lane >> 4);   // 8 rows per warp
    const float4* mem4 = (const float4*)(memory + (size_t)b * NN * MM);

    // memory is a kernel INPUT (no dependency) — stream it before the sync
    float4 v[4];
    #pragma unroll
    for (int i = 0; i < 4; i++)
        v[i] = mem4[(size_t)(rbase + 2 * i) * 16 + (lane & 15)];

    cudaGridDependencySynchronize();

    __shared__ float sk[MM];
    if (threadIdx.x < MM) sk[threadIdx.x] = g_k[phase][b * MM + threadIdx.x];
    __syncthreads();
    float4 kq = ((const float4*)sk)[lane & 15];
    float binvnk = g_binvnk[phase][b];
    float* out = g_logits + b * NN;

    #pragma unroll
    for (int i = 0; i < 4; i++) {
        float d = kq.x * v[i].x + kq.y * v[i].y + kq.z * v[i].z + kq.w * v[i].w;
        float s = v[i].x * v[i].x + v[i].y * v[i].y + v[i].z * v[i].z + v[i].w * v[i].w;
        #pragma unroll
        for (int o = 8; o > 0; o >>= 1) {
            d += __shfl_xor_sync(0xffffffffu, d, o);
            s += __shfl_xor_sync(0xffffffffu, s, o);
        }
        if ((lane & 15) == 0) out[rbase + 2 * i] = binvnk * d / (sqrtf(s) + EPSF);
    }
    cudaTriggerProgrammaticLaunchCompletion();
}

// ---- addressing (head only): softmax -> interp -> conv -> sharpen -> norm ----
__global__ __launch_bounds__(1024, 1)
void address_kernel(const float* __restrict__ w_tm1, float* __restrict__ head_out, int phase)
{
    extern __shared__ float sInter[];     // NN floats (64 KB)
    __shared__ float red[32];
    int b = blockIdx.x, t = threadIdx.x;
    int warp = t >> 5, lane = t & 31;

    cudaGridDependencySynchronize();
    const float* lg = g_logits + b * NN;

    float v[16];
    float lmax = -1e30f;
    #pragma unroll
    for (int e = 0; e < 16; e++) { v[e] = lg[e * 1024 + t]; lmax = fmaxf(lmax, v[e]); }
    #pragma unroll
    for (int o = 16; o > 0; o >>= 1) lmax = fmaxf(lmax, __shfl_xor_sync(0xffffffffu, lmax, o));
    if (lane == 0) red[warp] = lmax;
    __syncthreads();
    if (warp == 0) {
        float m = red[lane];
        #pragma unroll
        for (int o = 16; o > 0; o >>= 1) m = fmaxf(m, __shfl_xor_sync(0xffffffffu, m, o));
        red[lane] = m;
    }
    __syncthreads();
    float gmax = red[0];

    float lsum = 0.f;
    #pragma unroll
    for (int e = 0; e < 16; e++) { float ev = __expf(v[e] - gmax); v[e] = ev; lsum += ev; }
    #pragma unroll
    for (int o = 16; o > 0; o >>= 1) lsum += __shfl_xor_sync(0xffffffffu, lsum, o);
    __syncthreads();                      // red reusable
    if (lane == 0) red[warp] = lsum;
    __syncthreads();
    if (warp == 0) {
        float s = red[lane];
        #pragma unroll
        for (int o = 16; o > 0; o >>= 1) s += __shfl_xor_sync(0xffffffffu, s, o);
        red[lane] = s;
    }
    __syncthreads();
    float inv = 1.f / red[0];

    float gg = g_g[phase][b];
    const float* wt = w_tm1 + b * NN;
    #pragma unroll
    for (int e = 0; e < 16; e++) {
        int idx = e * 1024 + t;
        sInter[idx] = gg * v[e] * inv + (1.f - gg) * wt[idx];
    }
    __syncthreads();

    float s0 = g_s3[phase][b * SS + 0];
    float s1 = g_s3[phase][b * SS + 1];
    float s2 = g_s3[phase][b * SS + 2];
    float gamma = g_gamma[phase][b];
    float ssum = 0.f;
    #pragma unroll
    for (int e = 0; e < 16; e++) {
        int idx = e * 1024 + t;
        float c = s0 * sInter[(idx + NN - 2) & (NN - 1)]
                + s1 * sInter[(idx + NN - 1) & (NN - 1)]
                + s2 * sInter[idx];
        float sp = __powf(fmaxf(c, 1e-8f), gamma);
        v[e] = sp; ssum += sp;
    }
    #pragma unroll
    for (int o = 16; o > 0; o >>= 1) ssum += __shfl_xor_sync(0xffffffffu, ssum, o);
    __syncthreads();
    if (lane == 0) red[warp] = ssum;
    __syncthreads();
    if (warp == 0) {
        float s = red[lane];
        #pragma unroll
        for (int o = 16; o > 0; o >>= 1) s += __shfl_xor_sync(0xffffffffu, s, o);
        red[lane] = s;
    }
    __syncthreads();
    float invs = 1.f / red[0];
    float* out = head_out + b * NN;
    #pragma unroll
    for (int e = 0; e < 16; e++) out[e * 1024 + t] = v[e] * invs;
    cudaTriggerProgrammaticLaunchCompletion();
}

// -------- M_read partials: PDL prefetch of first 8 memory iterations ------
__global__ void mread_partial_kernel(const float* __restrict__ memory,
                                     const float* __restrict__ head)
{
    int b = blockIdx.y, cz = blockIdx.x;
    int t = threadIdx.x;          // 256
    int r = t >> 4, q = t & 15;   // 16 rows in flight x 16 float4 lanes
    const float4* mem4 = (const float4*)(memory + (size_t)b * NN * MM);
    int n0 = cz * ROWS_PER_CHUNK;

    // memory is an INPUT tensor (no dependency on address_kernel output):
    // stream the first 8 iterations' rows before the grid sync so the DRAM
    // pass overlaps the predecessor's drain.
    float4 pre[8];
    #pragma unroll
    for (int j = 0; j < 8; j++)
        pre[j] = mem4[(size_t)(n0 + j * 16 + r) * 16 + q];

    cudaGridDependencySynchronize();

    const float* hd = head + b * NN;
    float4 acc = make_float4(0.f, 0.f, 0.f, 0.f);
    #pragma unroll
    for (int j = 0; j < 8; j++) {
        float w = hd[n0 + j * 16 + r];
        acc.x += w * pre[j].x; acc.y += w * pre[j].y;
        acc.z += w * pre[j].z; acc.w += w * pre[j].w;
    }
    #pragma unroll
    for (int j = 8; j < 16; j++) {
        int n = n0 + j * 16 + r;
        float w = hd[n];
        float4 mv = mem4[(size_t)n * 16 + q];
        acc.x += w * mv.x; acc.y += w * mv.y; acc.z += w * mv.z; acc.w += w * mv.w;
    }
    __shared__ float4 sm[16][16];
    sm[r][q] = acc;
    __syncthreads();
    if (t < 16) {
        float4 s = sm[0][t];
        #pragma unroll
        for (int r2 = 1; r2 < 16; r2++) {
            float4 vv = sm[r2][t];
            s.x += vv.x; s.y += vv.y; s.z += vv.z; s.w += vv.w;
        }
        ((float4*)(g_Mpart + ((size_t)cz * BB + b) * MM))[t] = s;
    }
}

__global__ void mread_reduce_kernel()
{
    cudaGridDependencySynchronize();
    int i = blockIdx.x * 256 + threadIdx.x;   // BB*MM = 4096
    float s = 0.f;
    #pragma unroll 8
    for (int c = 0; c < CHUNKS; c++) s += g_Mpart[c * BB * MM + i];
    g_Mread[i] = s;
}

// ---------- gates GEMM tile body (one 64-wide K chunk = ky) ---------------
__device__ __forceinline__ void gates_chunk(const float* __restrict__ inp,
                                            const float* __restrict__ h_tm1,
                                            const float* __restrict__ W_ih,
                                            const float* __restrict__ W_hh,
                                            int jbase, int ky, int t)
{
    __shared__ __align__(16) float xs[32][68];   // [kk][batch]
    __shared__ __align__(16) float ws[32][68];   // [kk][jrow]
    int tj = t & 15, tb = t >> 4;
    float acc[4][4];
    #pragma unroll
    for (int jj = 0; jj < 4; jj++)
        #pragma unroll
        for (int bb2 = 0; bb2 < 4; bb2++) acc[jj][bb2] = 0.f;

    int kend = (ky + 1) * 64;
    for (int k0 = ky * 64; k0 < kend; k0 += 32) {
        #pragma unroll
        for (int li = t; li < 2048; li += 256) {
            int row = li >> 5, kk = li & 31, k = k0 + kk;
            float xv;
            if (k < DD)            xv = inp[row * DD + k];
            else if (k < DD + MM)  xv = g_Mread[row * MM + (k - DD)];
            else                   xv = h_tm1[row * HH + (k - DD - MM)];
            xs[kk][row] = xv;
            int j = jbase + row;
            float wv = (k < DD + MM) ? W_ih[j * (DD + MM) + k]
                                     : W_hh[j * HH + (k - DD - MM)];
            ws[kk][row] = wv;
        }
        __syncthreads();
        #pragma unroll
        for (int kk = 0; kk < 32; kk++) {
            float4 wr = *(const float4*)&ws[kk][tj * 4];
            float4 xr = *(const float4*)&xs[kk][tb * 4];
            acc[0][0] += wr.x * xr.x; acc[0][1] += wr.x * xr.y;
            acc[0][2] += wr.x * xr.z; acc[0][3] += wr.x * xr.w;
            acc[1][0] += wr.y * xr.x; acc[1][1] += wr.y * xr.y;
            acc[1][2] += wr.y * xr.z; acc[1][3] += wr.y * xr.w;
            acc[2][0] += wr.z * xr.x; acc[2][1] += wr.z * xr.y;
            acc[2][2] += wr.z * xr.z; acc[2][3] += wr.z * xr.w;
            acc[3][0] += wr.w * xr.x; acc[3][1] += wr.w * xr.y;
            acc[3][2] += wr.w * xr.z; acc[3][3] += wr.w * xr.w;
        }
        __syncthreads();
    }
    #pragma unroll
    for (int jj = 0; jj < 4; jj++) {
        int j = jbase + tj * 4 + jj;
        #pragma unroll
        for (int bb2 = 0; bb2 < 4; bb2++) {
            int b = tb * 4 + bb2;
            g_gates[((size_t)ky * BB + b) * G4H + j] = acc[jj][bb2];
        }
    }
}

// gates_main: the 12 chunks that need only inp + h_tm1 (no Mread)
__global__ void gates_main_kernel(const float* __restrict__ inp,
                                  const float* __restrict__ h_tm1,
                                  const float* __restrict__ W_ih,
                                  const float* __restrict__ W_hh)
{
    int ky = blockIdx.y < 4 ? blockIdx.y : blockIdx.y + 1;   // skip chunk 4
    gates_chunk(inp, h_tm1, W_ih, W_hh, blockIdx.x * 64, ky, threadIdx.x);
}

// gates_mr: chunk 4 (k in [256,320)) — depends on g_Mread
__global__ void gates_mr_kernel(const float* __restrict__ inp,
                                const float* __restrict__ h_tm1,
                                const float* __restrict__ W_ih,
                                const float* __restrict__ W_hh)
{
    cudaGridDependencySynchronize();
    gates_chunk(inp, h_tm1, W_ih, W_hh, blockIdx.x * 64, 4, threadIdx.x);
}

// ------------- memory update: PDL prefetch of memory ----------------------
__global__ void memupdate_kernel(const float* __restrict__ memory,
                                 const float* __restrict__ whead,
                                 float* __restrict__ mout)
{
    size_t i4 = (size_t)blockIdx.x * 256 + threadIdx.x;  // total BB*NN*MM/4
    int b   = (int)(i4 >> 18);                // NN*MM/4 = 262144
    int rem = (int)(i4 & 262143);
    int n   = rem >> 4;
    int mq  = rem & 15;
    float4 mv = ((const float4*)memory)[i4];   // input tensor: no dependency
    cudaGridDependencySynchronize();
    float w = whead[b * NN + n];
    float4 ev = ((const float4*)(g_e + b * MM))[mq];
    float4 av = ((const float4*)(g_a + b * MM))[mq];
    float4 o;
    o.x = mv.x * (1.f - w * ev.x) + w * av.x;
    o.y = mv.y * (1.f - w * ev.y) + w * av.y;
    o.z = mv.z * (1.f - w * ev.z) + w * av.z;
    o.w = mv.w * (1.f - w * ev.w) + w * av.w;
    __stcs(((float4*)mout) + i4, o);
}

// ---------------- side-stream resources (host-side only) ------------------
struct SideStream {
    cudaStream_t s;
    cudaEvent_t fork_ev, join_ev;
    SideStream() {
        cudaStreamCreateWithFlags(&s, cudaStreamNonBlocking);
        cudaEventCreateWithFlags(&fork_ev, cudaEventDisableTiming);
        cudaEventCreateWithFlags(&join_ev, cudaEventDisableTiming);
    }
};

// ---------------- PDL launch helper ---------------------------------------
template <typename F, typename... Args>
static inline void launch_pdl(F kernel, dim3 grid, dim3 block, size_t smem, Args... args)
{
    cudaLaunchConfig_t cfg = {};
    cfg.gridDim = grid;
    cfg.blockDim = block;
    cfg.dynamicSmemBytes = smem;
    cfg.stream = 0;
    cudaLaunchAttribute attr[1];
    attr[0].id = cudaLaunchAttributeProgrammaticStreamSerialization;
    attr[0].val.programmaticStreamSerializationAllowed = 1;
    cfg.attrs = attr;
    cfg.numAttrs = 1;
    cudaLaunchKernelEx(&cfg, kernel, args...);
}

// --------------------------------- launch ---------------------------------
extern "C" void kernel_launch(void* const* d_in, const int* in_sizes, int n_in,
                              void* d_out_v, int out_size)
{
    const float* inp       = (const float*)d_in[0];
    const float* h_tm1     = (const float*)d_in[1];
    const float* c_tm1     = (const float*)d_in[2];
    const float* read_tm1  = (const float*)d_in[3];
    const float* write_tm1 = (const float*)d_in[4];
    const float* memory    = (const float*)d_in[5];
    const float* W_ih = (const float*)d_in[6];
    const float* b_ih = (const float*)d_in[7];
    const float* W_hh = (const float*)d_in[8];
    const float* b_hh = (const float*)d_in[9];
    const float* W_rk = (const float*)d_in[10];
    const float* b_rk = (const float*)d_in[11];
    const float* W_wk = (const float*)d_in[12];
    const float* b_wk = (const float*)d_in[13];
    const float* W_rc = (const float*)d_in[14];
    const float* b_rc = (const float*)d_in[15];
    const float* W_wc = (const float*)d_in[16];
    const float* b_wc = (const float*)d_in[17];
    const float* W_rs = (const float*)d_in[18];
    const float* b_rs = (const float*)d_in[19];
    const float* W_ws = (const float*)d_in[20];
    const float* b_ws = (const float*)d_in[21];
    const float* W_w  = (const float*)d_in[22];
    const float* b_w  = (const float*)d_in[23];

    float* d_out = (float*)d_out_v;
    float* rhead  = d_out + 2 * BB * HH;
    float* whead  = rhead + (size_t)BB * NN;
    float* mout   = whead + (size_t)BB * NN;
    (void)in_sizes; (void)n_in; (void)out_size;

    static SideStream side;               // created once (host resources only)

    cudaFuncSetAttribute(address_kernel,
                         cudaFuncAttributeMaxDynamicSharedMemorySize, NN * 4);

    // ---- fork: gates_main runs concurrently with the read phase ----
    cudaEventRecord(side.fork_ev, 0);
    cudaStreamWaitEvent(side.s, side.fork_ev, 0);
    gates_main_kernel<<<dim3(G4H / 64, KSPLIT - 1), 256, 0, side.s>>>(inp, h_tm1, W_ih, W_hh);
    cudaEventRecord(side.join_ev, side.s);

    // ---- read phase (main stream, PDL-chained) ----
    head_params_kernel<<<BB, 512>>>(h_tm1, W_rk, b_rk, W_rc, b_rc, W_rs, b_rs, 0,
                                    nullptr, nullptr, nullptr, nullptr, nullptr, nullptr);
    launch_pdl(logits_kernel, dim3(NN / 64, BB), dim3(256), 0, memory, 0);
    launch_pdl(address_kernel, dim3(BB), dim3(1024), (size_t)NN * 4,
               (const float*)read_tm1, rhead, 0);
    launch_pdl(mread_partial_kernel, dim3(CHUNKS, BB), dim3(256), 0,
               memory, (const float*)rhead);
    launch_pdl(mread_reduce_kernel, dim3(BB * MM / 256), dim3(256), 0);

    // ---- LSTM gates ----
    launch_pdl(gates_mr_kernel, dim3(G4H / 64, 1), dim3(256), 0, inp, h_tm1, W_ih, W_hh);
    cudaStreamWaitEvent(0, side.join_ev, 0);     // join gates_main before fused lstm

    // ---- write phase: head_params_w computes lstm + head params in one ----
    head_params_kernel<<<BB, 512>>>(nullptr, W_wk, b_wk, W_wc, b_wc, W_ws, b_ws, 1,
                                    W_w, b_w, c_tm1, b_ih, b_hh, d_out);
    launch_pdl(logits_kernel, dim3(NN / 64, BB), dim3(256), 0, memory, 1);
    launch_pdl(address_kernel, dim3(BB), dim3(1024), (size_t)NN * 4,
               (const float*)write_tm1, whead, 1);
    launch_pdl(memupdate_kernel, dim3((BB * NN * MM / 4) / 256), dim3(256), 0,
               memory, (const float*)whead, mout);
}

// round 17
// speedup vs baseline: 1.0463x; 1.0124x over previous
#include <cuda_runtime.h>
#include <math.h>

#define BB 64
#define DD 256
#define HH 512
#define NN 16384
#define MM 64
#define SS 3
#define EPSF 1e-4f
#define G4H 2048
#define KTOT 832            // D + M + H
#define KSPLIT 13           // 832 = 13 * 64
#define CHUNKS 64
#define ROWS_PER_CHUNK (NN / CHUNKS)   // 256

// ---------------- scratch (device globals, no allocation) ----------------
__device__ float g_k[2][BB * MM];        // tanh keys (read=0, write=1)
__device__ float g_s3[2][BB * SS];       // shift softmax
__device__ float g_binvnk[2][BB];        // beta / nk
__device__ float g_g[2][BB];
__device__ float g_gamma[2][BB];
__device__ float g_e[BB * MM];
__device__ float g_a[BB * MM];
__device__ float g_logits[BB * NN];
__device__ float g_Mpart[CHUNKS * BB * MM];
__device__ float g_Mread[BB * MM];
__device__ float g_gates[KSPLIT * BB * G4H];   // K-split partials (no bias)

// ============ head params: warp-per-row coalesced GEMV, 16 warps ==========
// Read phase (Ww==null): h comes from hvec (h_tm1).
// Write phase (Ww!=null): h_t computed HERE (fused LSTM) from g_gates.
__global__ void head_params_kernel(const float* __restrict__ hvec,
                                   const float* __restrict__ Wk, const float* __restrict__ bk,
                                   const float* __restrict__ Wc, const float* __restrict__ bc,
                                   const float* __restrict__ Ws, const float* __restrict__ bs,
                                   int phase,
                                   const float* __restrict__ Ww, const float* __restrict__ bw,
                                   const float* __restrict__ c_tm1,
                                   const float* __restrict__ b_ih,
                                   const float* __restrict__ b_hh,
                                   float* __restrict__ d_out)
{
    int b = blockIdx.x;
    int t = threadIdx.x;                 // 512 threads = 16 warps
    int warp = t >> 5, lane = t & 31;
    __shared__ float sh[HH];
    __shared__ float sk[MM];
    __shared__ float sc[SS];
    __shared__ float ssl[SS];

    if (Ww) {
        // ---- fused LSTM: thread t handles hidden index j = t ----
        int j = t;
        float gv[4];
        #pragma unroll
        for (int g = 0; g < 4; g++) {
            int col = g * HH + j;
            float s = b_ih[col] + b_hh[col];
            #pragma unroll
            for (int s4 = 0; s4 < KSPLIT; s4++)
                s += g_gates[((size_t)s4 * BB + b) * G4H + col];
            gv[g] = s;
        }
        float si = 1.f / (1.f + expf(-gv[0]));
        float sf = 1.f / (1.f + expf(-gv[1]));
        float so = 1.f / (1.f + expf(-gv[3]));
        float ct = sf * c_tm1[b * HH + j] + si * tanhf(gv[2]);
        float ht = so * tanhf(ct);
        d_out[b * HH + j] = ht;               // h_t
        d_out[BB * HH + b * HH + j] = ct;     // c_t
        sh[j] = ht;                           // straight into the GEMV input
    } else {
        sh[t] = hvec[b * HH + t];
    }
    __syncthreads();

    int nrows = Ww ? 198 : 70;
    for (int rr = warp; rr < nrows; rr += 16) {
        const float* w;
        if (rr < 64)       w = Wk + rr * HH;
        else if (rr < 67)  w = Wc + (rr - 64) * HH;
        else if (rr < 70)  w = Ws + (rr - 67) * HH;
        else               w = Ww + (rr - 70) * HH;
        float acc = 0.f;
        #pragma unroll
        for (int it = 0; it < 16; it++) {
            int kx = lane + it * 32;
            acc += sh[kx] * w[kx];
        }
        #pragma unroll
        for (int o = 16; o > 0; o >>= 1) acc += __shfl_down_sync(0xffffffffu, acc, o);
        if (lane == 0) {
            if (rr < 64) {
                float kv = tanhf(acc + bk[rr]);
                sk[rr] = kv;
                g_k[phase][b * MM + rr] = kv;
            } else if (rr < 67) {
                sc[rr - 64] = acc + bc[rr - 64];
            } else if (rr < 70) {
                ssl[rr - 67] = acc + bs[rr - 67];
            } else {
                int r = rr - 70;
                float v = acc + bw[r];
                if (r < MM) g_e[b * MM + r] = 1.f / (1.f + expf(-v));
                else        g_a[b * MM + (r - MM)] = v;
            }
        }
    }
    __syncthreads();

    if (t == 0) {
        float mx = fmaxf(ssl[0], fmaxf(ssl[1], ssl[2]));
        float e0 = expf(ssl[0] - mx), e1 = expf(ssl[1] - mx), e2 = expf(ssl[2] - mx);
        float sum = e0 + e1 + e2;
        g_s3[phase][b * SS + 0] = e0 / sum;
        g_s3[phase][b * SS + 1] = e1 / sum;
        g_s3[phase][b * SS + 2] = e2 / sum;
        float beta  = fmaxf(sc[0], 0.f) + EPSF;
        float gv    = 1.f / (1.f + expf(-sc[1]));
        float gamma = fmaxf(sc[2], 0.f) + 1.f + EPSF;
        float ns = 0.f;
        for (int i = 0; i < MM; i++) ns += sk[i] * sk[i];
        float nk = sqrtf(ns) + EPSF;
        g_binvnk[phase][b] = beta / nk;
        g_g[phase][b] = gv;
        g_gamma[phase][b] = gamma;
    }
    cudaTriggerProgrammaticLaunchCompletion();
}

// ------------- logits: PDL prefetch of memory before grid sync ------------
__global__ void logits_kernel(const float* __restrict__ memory, int phase)
{
    int b = blockIdx.y;
    int warp = threadIdx.x >> 5, lane = threadIdx.x & 31;
    int rbase = blockIdx.x * 64 + warp * 8 + (lane >> 4);   // 8 rows per warp
    const float4* mem4 = (const float4*)(memory + (size_t)b * NN * MM);

    // memory is a kernel INPUT (no dependency) — stream it before the sync
    float4 v[4];
    #pragma unroll
    for (int i = 0; i < 4; i++)
        v[i] = mem4[(size_t)(rbase + 2 * i) * 16 + (lane & 15)];

    cudaGridDependencySynchronize();

    __shared__ float sk[MM];
    if (threadIdx.x < MM) sk[threadIdx.x] = g_k[phase][b * MM + threadIdx.x];
    __syncthreads();
    float4 kq = ((const float4*)sk)[lane & 15];
    float binvnk = g_binvnk[phase][b];
    float* out = g_logits + b * NN;

    #pragma unroll
    for (int i = 0; i < 4; i++) {
        float d = kq.x * v[i].x + kq.y * v[i].y + kq.z * v[i].z + kq.w * v[i].w;
        float s = v[i].x * v[i].x + v[i].y * v[i].y + v[i].z * v[i].z + v[i].w * v[i].w;
        #pragma unroll
        for (int o = 8; o > 0; o >>= 1) {
            d += __shfl_xor_sync(0xffffffffu, d, o);
            s += __shfl_xor_sync(0xffffffffu, s, o);
        }
        if ((lane & 15) == 0) out[rbase + 2 * i] = binvnk * d / (sqrtf(s) + EPSF);
    }
    cudaTriggerProgrammaticLaunchCompletion();
}

// ---- addressing: softmax -> interp -> conv -> sharpen -> norm.
//      w_tm1 (input tensor) is prefetched BEFORE the grid sync.
__global__ __launch_bounds__(1024, 1)
void address_kernel(const float* __restrict__ w_tm1, float* __restrict__ head_out, int phase)
{
    extern __shared__ float sInter[];     // NN floats (64 KB)
    __shared__ float red[32];
    int b = blockIdx.x, t = threadIdx.x;
    int warp = t >> 5, lane = t & 31;

    // prefetch interpolation source (input tensor, no dependency)
    const float* wt = w_tm1 + b * NN;
    float wv[16];
    #pragma unroll
    for (int e = 0; e < 16; e++) wv[e] = wt[e * 1024 + t];

    cudaGridDependencySynchronize();
    const float* lg = g_logits + b * NN;

    float v[16];
    float lmax = -1e30f;
    #pragma unroll
    for (int e = 0; e < 16; e++) { v[e] = lg[e * 1024 + t]; lmax = fmaxf(lmax, v[e]); }
    #pragma unroll
    for (int o = 16; o > 0; o >>= 1) lmax = fmaxf(lmax, __shfl_xor_sync(0xffffffffu, lmax, o));
    if (lane == 0) red[warp] = lmax;
    __syncthreads();
    if (warp == 0) {
        float m = red[lane];
        #pragma unroll
        for (int o = 16; o > 0; o >>= 1) m = fmaxf(m, __shfl_xor_sync(0xffffffffu, m, o));
        red[lane] = m;
    }
    __syncthreads();
    float gmax = red[0];

    float lsum = 0.f;
    #pragma unroll
    for (int e = 0; e < 16; e++) { float ev = __expf(v[e] - gmax); v[e] = ev; lsum += ev; }
    #pragma unroll
    for (int o = 16; o > 0; o >>= 1) lsum += __shfl_xor_sync(0xffffffffu, lsum, o);
    __syncthreads();                      // red reusable
    if (lane == 0) red[warp] = lsum;
    __syncthreads();
    if (warp == 0) {
        float s = red[lane];
        #pragma unroll
        for (int o = 16; o > 0; o >>= 1) s += __shfl_xor_sync(0xffffffffu, s, o);
        red[lane] = s;
    }
    __syncthreads();
    float inv = 1.f / red[0];

    float gg = g_g[phase][b];
    #pragma unroll
    for (int e = 0; e < 16; e++) {
        int idx = e * 1024 + t;
        sInter[idx] = gg * v[e] * inv + (1.f - gg) * wv[e];
    }
    __syncthreads();

    float s0 = g_s3[phase][b * SS + 0];
    float s1 = g_s3[phase][b * SS + 1];
    float s2 = g_s3[phase][b * SS + 2];
    float gamma = g_gamma[phase][b];
    float ssum = 0.f;
    #pragma unroll
    for (int e = 0; e < 16; e++) {
        int idx = e * 1024 + t;
        float c = s0 * sInter[(idx + NN - 2) & (NN - 1)]
                + s1 * sInter[(idx + NN - 1) & (NN - 1)]
                + s2 * sInter[idx];
        float sp = __powf(fmaxf(c, 1e-8f), gamma);
        v[e] = sp; ssum += sp;
    }
    #pragma unroll
    for (int o = 16; o > 0; o >>= 1) ssum += __shfl_xor_sync(0xffffffffu, ssum, o);
    __syncthreads();
    if (lane == 0) red[warp] = ssum;
    __syncthreads();
    if (warp == 0) {
        float s = red[lane];
        #pragma unroll
        for (int o = 16; o > 0; o >>= 1) s += __shfl_xor_sync(0xffffffffu, s, o);
        red[lane] = s;
    }
    __syncthreads();
    float invs = 1.f / red[0];
    float* out = head_out + b * NN;
    #pragma unroll
    for (int e = 0; e < 16; e++) out[e * 1024 + t] = v[e] * invs;
    cudaTriggerProgrammaticLaunchCompletion();
}

// -------- M_read partials: PDL prefetch of first 8 memory iterations ------
__global__ void mread_partial_kernel(const float* __restrict__ memory,
                                     const float* __restrict__ head)
{
    int b = blockIdx.y, cz = blockIdx.x;
    int t = threadIdx.x;          // 256
    int r = t >> 4, q = t & 15;   // 16 rows in flight x 16 float4 lanes
    const float4* mem4 = (const float4*)(memory + (size_t)b * NN * MM);
    int n0 = cz * ROWS_PER_CHUNK;

    // memory is an INPUT tensor: stream first 8 iterations before the sync
    float4 pre[8];
    #pragma unroll
    for (int j = 0; j < 8; j++)
        pre[j] = mem4[(size_t)(n0 + j * 16 + r) * 16 + q];

    cudaGridDependencySynchronize();

    const float* hd = head + b * NN;
    float4 acc = make_float4(0.f, 0.f, 0.f, 0.f);
    #pragma unroll
    for (int j = 0; j < 8; j++) {
        float w = hd[n0 + j * 16 + r];
        acc.x += w * pre[j].x; acc.y += w * pre[j].y;
        acc.z += w * pre[j].z; acc.w += w * pre[j].w;
    }
    #pragma unroll
    for (int j = 8; j < 16; j++) {
        int n = n0 + j * 16 + r;
        float w = hd[n];
        float4 mv = mem4[(size_t)n * 16 + q];
        acc.x += w * mv.x; acc.y += w * mv.y; acc.z += w * mv.z; acc.w += w * mv.w;
    }
    __shared__ float4 sm[16][16];
    sm[r][q] = acc;
    __syncthreads();
    if (t < 16) {
        float4 s = sm[0][t];
        #pragma unroll
        for (int r2 = 1; r2 < 16; r2++) {
            float4 vv = sm[r2][t];
            s.x += vv.x; s.y += vv.y; s.z += vv.z; s.w += vv.w;
        }
        ((float4*)(g_Mpart + ((size_t)cz * BB + b) * MM))[t] = s;
    }
}

__global__ void mread_reduce_kernel()
{
    cudaGridDependencySynchronize();
    int i = blockIdx.x * 256 + threadIdx.x;   // BB*MM = 4096
    float s = 0.f;
    #pragma unroll 8
    for (int c = 0; c < CHUNKS; c++) s += g_Mpart[c * BB * MM + i];
    g_Mread[i] = s;
}

// ---------- gates GEMM tile body (one 64-wide K chunk = ky) ---------------
__device__ __forceinline__ void gates_chunk(const float* __restrict__ inp,
                                            const float* __restrict__ h_tm1,
                                            const float* __restrict__ W_ih,
                                            const float* __restrict__ W_hh,
                                            int jbase, int ky, int t)
{
    __shared__ __align__(16) float xs[32][68];   // [kk][batch]
    __shared__ __align__(16) float ws[32][68];   // [kk][jrow]
    int tj = t & 15, tb = t >> 4;
    float acc[4][4];
    #pragma unroll
    for (int jj = 0; jj < 4; jj++)
        #pragma unroll
        for (int bb2 = 0; bb2 < 4; bb2++) acc[jj][bb2] = 0.f;

    int kend = (ky + 1) * 64;
    for (int k0 = ky * 64; k0 < kend; k0 += 32) {
        #pragma unroll
        for (int li = t; li < 2048; li += 256) {
            int row = li >> 5, kk = li & 31, k = k0 + kk;
            float xv;
            if (k < DD)            xv = inp[row * DD + k];
            else if (k < DD + MM)  xv = g_Mread[row * MM + (k - DD)];
            else                   xv = h_tm1[row * HH + (k - DD - MM)];
            xs[kk][row] = xv;
            int j = jbase + row;
            float wv = (k < DD + MM) ? W_ih[j * (DD + MM) + k]
                                     : W_hh[j * HH + (k - DD - MM)];
            ws[kk][row] = wv;
        }
        __syncthreads();
        #pragma unroll
        for (int kk = 0; kk < 32; kk++) {
            float4 wr = *(const float4*)&ws[kk][tj * 4];
            float4 xr = *(const float4*)&xs[kk][tb * 4];
            acc[0][0] += wr.x * xr.x; acc[0][1] += wr.x * xr.y;
            acc[0][2] += wr.x * xr.z; acc[0][3] += wr.x * xr.w;
            acc[1][0] += wr.y * xr.x; acc[1][1] += wr.y * xr.y;
            acc[1][2] += wr.y * xr.z; acc[1][3] += wr.y * xr.w;
            acc[2][0] += wr.z * xr.x; acc[2][1] += wr.z * xr.y;
            acc[2][2] += wr.z * xr.z; acc[2][3] += wr.z * xr.w;
            acc[3][0] += wr.w * xr.x; acc[3][1] += wr.w * xr.y;
            acc[3][2] += wr.w * xr.z; acc[3][3] += wr.w * xr.w;
        }
        __syncthreads();
    }
    #pragma unroll
    for (int jj = 0; jj < 4; jj++) {
        int j = jbase + tj * 4 + jj;
        #pragma unroll
        for (int bb2 = 0; bb2 < 4; bb2++) {
            int b = tb * 4 + bb2;
            g_gates[((size_t)ky * BB + b) * G4H + j] = acc[jj][bb2];
        }
    }
}

// gates_main: the 12 chunks that need only inp + h_tm1 (no Mread)
__global__ void gates_main_kernel(const float* __restrict__ inp,
                                  const float* __restrict__ h_tm1,
                                  const float* __restrict__ W_ih,
                                  const float* __restrict__ W_hh)
{
    int ky = blockIdx.y < 4 ? blockIdx.y : blockIdx.y + 1;   // skip chunk 4
    gates_chunk(inp, h_tm1, W_ih, W_hh, blockIdx.x * 64, ky, threadIdx.x);
}

// gates_mr: chunk 4 (k in [256,320)) — depends on g_Mread
__global__ void gates_mr_kernel(const float* __restrict__ inp,
                                const float* __restrict__ h_tm1,
                                const float* __restrict__ W_ih,
                                const float* __restrict__ W_hh)
{
    cudaGridDependencySynchronize();
    gates_chunk(inp, h_tm1, W_ih, W_hh, blockIdx.x * 64, 4, threadIdx.x);
}

// ------ memory update: 4 float4/thread, deep PDL prefetch of memory -------
__global__ void memupdate_kernel(const float* __restrict__ memory,
                                 const float* __restrict__ whead,
                                 float* __restrict__ mout)
{
    size_t base = (size_t)blockIdx.x * 1024 + threadIdx.x;   // 4 float4 per thread
    int b  = (int)(base >> 18);               // NN*MM/4 = 262144 float4 per b
    int mq = threadIdx.x & 15;                // same for all 4 (stride 256)

    // memory is an INPUT tensor: batch all 4 loads before the sync so the
    // DRAM stream overlaps the address_w drain.
    float4 mv[4];
    #pragma unroll
    for (int k = 0; k < 4; k++)
        mv[k] = ((const float4*)memory)[base + (size_t)k * 256];

    cudaGridDependencySynchronize();

    const float* wh = whead + b * NN;
    float wv[4];
    #pragma unroll
    for (int k = 0; k < 4; k++) {
        size_t i4 = base + (size_t)k * 256;
        wv[k] = wh[(int)(i4 & 262143) >> 4];
    }
    float4 ev = ((const float4*)(g_e + b * MM))[mq];
    float4 av = ((const float4*)(g_a + b * MM))[mq];
    #pragma unroll
    for (int k = 0; k < 4; k++) {
        float w = wv[k];
        float4 o;
        o.x = mv[k].x * (1.f - w * ev.x) + w * av.x;
        o.y = mv[k].y * (1.f - w * ev.y) + w * av.y;
        o.z = mv[k].z * (1.f - w * ev.z) + w * av.z;
        o.w = mv[k].w * (1.f - w * ev.w) + w * av.w;
        __stcs(((float4*)mout) + base + (size_t)k * 256, o);
    }
}

// ---------------- side-stream resources (host-side only) ------------------
struct SideStream {
    cudaStream_t s;
    cudaEvent_t fork_ev, join_ev;
    SideStream() {
        cudaStreamCreateWithFlags(&s, cudaStreamNonBlocking);
        cudaEventCreateWithFlags(&fork_ev, cudaEventDisableTiming);
        cudaEventCreateWithFlags(&join_ev, cudaEventDisableTiming);
    }
};

// ---------------- PDL launch helper ---------------------------------------
template <typename F, typename... Args>
static inline void launch_pdl(F kernel, dim3 grid, dim3 block, size_t smem, Args... args)
{
    cudaLaunchConfig_t cfg = {};
    cfg.gridDim = grid;
    cfg.blockDim = block;
    cfg.dynamicSmemBytes = smem;
    cfg.stream = 0;
    cudaLaunchAttribute attr[1];
    attr[0].id = cudaLaunchAttributeProgrammaticStreamSerialization;
    attr[0].val.programmaticStreamSerializationAllowed = 1;
    cfg.attrs = attr;
    cfg.numAttrs = 1;
    cudaLaunchKernelEx(&cfg, kernel, args...);
}

// --------------------------------- launch ---------------------------------
extern "C" void kernel_launch(void* const* d_in, const int* in_sizes, int n_in,
                              void* d_out_v, int out_size)
{
    const float* inp       = (const float*)d_in[0];
    const float* h_tm1     = (const float*)d_in[1];
    const float* c_tm1     = (const float*)d_in[2];
    const float* read_tm1  = (const float*)d_in[3];
    const float* write_tm1 = (const float*)d_in[4];
    const float* memory    = (const float*)d_in[5];
    const float* W_ih = (const float*)d_in[6];
    const float* b_ih = (const float*)d_in[7];
    const float* W_hh = (const float*)d_in[8];
    const float* b_hh = (const float*)d_in[9];
    const float* W_rk = (const float*)d_in[10];
    const float* b_rk = (const float*)d_in[11];
    const float* W_wk = (const float*)d_in[12];
    const float* b_wk = (const float*)d_in[13];
    const float* W_rc = (const float*)d_in[14];
    const float* b_rc = (const float*)d_in[15];
    const float* W_wc = (const float*)d_in[16];
    const float* b_wc = (const float*)d_in[17];
    const float* W_rs = (const float*)d_in[18];
    const float* b_rs = (const float*)d_in[19];
    const float* W_ws = (const float*)d_in[20];
    const float* b_ws = (const float*)d_in[21];
    const float* W_w  = (const float*)d_in[22];
    const float* b_w  = (const float*)d_in[23];

    float* d_out = (float*)d_out_v;
    float* rhead  = d_out + 2 * BB * HH;
    float* whead  = rhead + (size_t)BB * NN;
    float* mout   = whead + (size_t)BB * NN;
    (void)in_sizes; (void)n_in; (void)out_size;

    static SideStream side;               // created once (host resources only)

    cudaFuncSetAttribute(address_kernel,
                         cudaFuncAttributeMaxDynamicSharedMemorySize, NN * 4);

    // ---- fork: gates_main runs concurrently with the read phase ----
    cudaEventRecord(side.fork_ev, 0);
    cudaStreamWaitEvent(side.s, side.fork_ev, 0);
    gates_main_kernel<<<dim3(G4H / 64, KSPLIT - 1), 256, 0, side.s>>>(inp, h_tm1, W_ih, W_hh);
    cudaEventRecord(side.join_ev, side.s);

    // ---- read phase (main stream, PDL-chained) ----
    head_params_kernel<<<BB, 512>>>(h_tm1, W_rk, b_rk, W_rc, b_rc, W_rs, b_rs, 0,
                                    nullptr, nullptr, nullptr, nullptr, nullptr, nullptr);
    launch_pdl(logits_kernel, dim3(NN / 64, BB), dim3(256), 0, memory, 0);
    launch_pdl(address_kernel, dim3(BB), dim3(1024), (size_t)NN * 4,
               (const float*)read_tm1, rhead, 0);
    launch_pdl(mread_partial_kernel, dim3(CHUNKS, BB), dim3(256), 0,
               memory, (const float*)rhead);
    launch_pdl(mread_reduce_kernel, dim3(BB * MM / 256), dim3(256), 0);

    // ---- LSTM gates ----
    launch_pdl(gates_mr_kernel, dim3(G4H / 64, 1), dim3(256), 0, inp, h_tm1, W_ih, W_hh);
    cudaStreamWaitEvent(0, side.join_ev, 0);     // join gates_main before fused lstm

    // ---- write phase: head_params_w computes lstm + head params in one ----
    head_params_kernel<<<BB, 512>>>(nullptr, W_wk, b_wk, W_wc, b_wc, W_ws, b_ws, 1,
                                    W_w, b_w, c_tm1, b_ih, b_hh, d_out);
    launch_pdl(logits_kernel, dim3(NN / 64, BB), dim3(256), 0, memory, 1);
    launch_pdl(address_kernel, dim3(BB), dim3(1024), (size_t)NN * 4,
               (const float*)write_tm1, whead, 1);
    launch_pdl(memupdate_kernel, dim3((BB * NN * MM / 4) / 1024), dim3(256), 0,
               memory, (const float*)whead, mout);
}